// round 14
// baseline (speedup 1.0000x reference)
#include <cuda_runtime.h>
#include <cuda_fp16.h>
#include <cstdint>

// Problem constants (fixed shapes per reference)
#define TOKENS 8192
#define INF    4096
#define OUTF   4096

// ---------------- device scratch (static globals; no runtime allocation) ----
__device__ __half         g_Wh[(size_t)OUTF * INF];     // 32 MiB fp16 W (scatter target)
__device__ unsigned short g_Xh[(size_t)TOKENS * INF];   // 64 MiB fp16 x
__device__ int            g_idx32_flag;                 // 1 => indices are int32

// ---------------- helpers ---------------------------------------------------
__device__ __forceinline__ uint32_t smem_to_u32(const void* p) {
    uint32_t a;
    asm("{ .reg .u64 t; cvta.to.shared.u64 t, %1; cvt.u32.u64 %0, t; }"
        : "=r"(a) : "l"(p));
    return a;
}

#define SMEM_SWIZZLE_128B(byte_offset) \
    ((byte_offset) ^ (((byte_offset) >> 3) & 0x70))

__device__ __forceinline__ void cp_async_16(uint32_t saddr, const void* gaddr) {
    asm volatile("cp.async.cg.shared.global [%0], [%1], 16;"
                 :: "r"(saddr), "l"(gaddr) : "memory");
}
#define CP_ASYNC_COMMIT() asm volatile("cp.async.commit_group;" ::: "memory")
#define CP_ASYNC_WAIT(N)  asm volatile("cp.async.wait_group %0;" :: "n"(N) : "memory")

__device__ __forceinline__ void ldsm_x4(uint32_t r[4], uint32_t addr) {
    asm volatile("ldmatrix.sync.aligned.m8n8.x4.shared.b16 {%0,%1,%2,%3}, [%4];"
                 : "=r"(r[0]), "=r"(r[1]), "=r"(r[2]), "=r"(r[3]) : "r"(addr));
}

__device__ __forceinline__ void mma16816(float c[4], const uint32_t a[4],
                                         uint32_t b0, uint32_t b1) {
    asm volatile(
        "mma.sync.aligned.m16n8k16.row.col.f32.f16.f16.f32 "
        "{%0,%1,%2,%3}, {%4,%5,%6,%7}, {%8,%9}, {%0,%1,%2,%3};"
        : "+f"(c[0]), "+f"(c[1]), "+f"(c[2]), "+f"(c[3])
        : "r"(a[0]), "r"(a[1]), "r"(a[2]), "r"(a[3]), "r"(b0), "r"(b1));
}

// ---------------- prep kernels ---------------------------------------------
__global__ void flag_reset_kernel() {
    if (threadIdx.x == 0) g_idx32_flag = 0;
}

__device__ __forceinline__ uint2 f4_to_h4(float4 v) {
    __half2 lo = __floats2half2_rn(v.x, v.y);
    __half2 hi = __floats2half2_rn(v.z, v.w);
    uint2 o;
    o.x = *reinterpret_cast<uint32_t*>(&lo);
    o.y = *reinterpret_cast<uint32_t*>(&hi);
    return o;
}

// One block-partitioned kernel running three independent DRAM-bound jobs
// concurrently: convert x -> fp16, zero fp16 W, detect index dtype on a 64K
// prefix. Dtype detection: reading the prefix as int64 is in-bounds under
// both interpretations; true-int64 row indices are < OUTF, packed-int32
// pairs overflow OUTF as soon as the high 32-bit lane is nonzero.
static constexpr int CONV_BLOCKS = 8192;
static constexpr int ZERO_BLOCKS = 1024;
static constexpr int DET_BLOCKS  = 256;

__global__ void fused_prep_kernel(const float* __restrict__ x,
                                  const long long* __restrict__ idx, int ndet) {
    const int b = blockIdx.x;
    if (b < CONV_BLOCKS) {
        size_t i = (size_t)b * 256 + threadIdx.x;
        const size_t stride = (size_t)CONV_BLOCKS * 256;
        float4 v0 = reinterpret_cast<const float4*>(x)[i];
        float4 v1 = reinterpret_cast<const float4*>(x)[i + stride];
        float4 v2 = reinterpret_cast<const float4*>(x)[i + 2 * stride];
        float4 v3 = reinterpret_cast<const float4*>(x)[i + 3 * stride];
        reinterpret_cast<uint2*>(g_Xh)[i]              = f4_to_h4(v0);
        reinterpret_cast<uint2*>(g_Xh)[i + stride]     = f4_to_h4(v1);
        reinterpret_cast<uint2*>(g_Xh)[i + 2 * stride] = f4_to_h4(v2);
        reinterpret_cast<uint2*>(g_Xh)[i + 3 * stride] = f4_to_h4(v3);
    } else if (b < CONV_BLOCKS + ZERO_BLOCKS) {
        size_t i = (size_t)(b - CONV_BLOCKS) * 256 + threadIdx.x;
        const size_t stride = (size_t)ZERO_BLOCKS * 256;
        uint4 z = make_uint4(0u, 0u, 0u, 0u);
#pragma unroll
        for (int j = 0; j < 8; j++)
            reinterpret_cast<uint4*>(g_Wh)[i + j * stride] = z;
    } else {
        int i = (b - CONV_BLOCKS - ZERO_BLOCKS) * 256 + threadIdx.x;
        if (i < ndet) {
            long long v = idx[i];
            if (v < 0 || v >= OUTF) atomicOr(&g_idx32_flag, 1);
        }
    }
}

// Scatter-add COO directly into fp16 W (duplicates summed via f16 atomics).
__global__ void scatter_kernel(const void* __restrict__ idx_raw,
                               const float* __restrict__ w, int nnz) {
    int i = blockIdx.x * blockDim.x + threadIdx.x;
    if (i >= nnz) return;
    long long r, c;
    if (g_idx32_flag) {
        const int* p = (const int*)idx_raw;
        r = p[i];
        c = p[(size_t)nnz + i];
    } else {
        const long long* p = (const long long*)idx_raw;
        r = p[i];
        c = p[(size_t)nnz + i];
    }
    if (r >= 0 && r < OUTF && c >= 0 && c < INF)
        atomicAdd(&g_Wh[(size_t)r * INF + c], __float2half(w[i]));
}

// ---------------- GEMM kernel (mma.sync m16n8k16) ---------------------------
// CTA tile 256(M) x 64(N) x 64(K); 256 threads = 8 warps as 4(M) x 2(N),
// warp tile 64x32. 2-stage cp.async double buffer, 40 KB/stage -> 80 KB/CTA
// => TWO CTAs per SM. Independent CTAs interleave their barrier/preload
// bubbles, keeping the tensor pipe fed (the R12/R13 single-CTA configs
// plateaued at ~73% tensor because all warps stalled at one barrier).

static constexpr int CTA_M  = 256;
static constexpr int CTA_N  = 64;
static constexpr int CTA_K  = 64;
static constexpr int KITERS = INF / CTA_K;   // 64
static constexpr int NTHREADS = 256;

static constexpr int A_BYTES      = CTA_M * CTA_K * 2;   // 32768
static constexpr int B_BYTES      = CTA_N * CTA_K * 2;   // 8192
static constexpr int STAGE_BYTES  = A_BYTES + B_BYTES;   // 40960
static constexpr int GEMM_SMEM    = 2 * STAGE_BYTES;     // 81920 per CTA

__device__ __forceinline__ void load_stage(uint32_t sbase, int tid,
                                           const unsigned short* __restrict__ Xp,
                                           const unsigned short* __restrict__ Wp,
                                           int slot, int kb) {
    const uint32_t stage = sbase + slot * STAGE_BYTES;
    const int kcol = kb * CTA_K;
#pragma unroll
    for (int j = 0; j < 10; j++) {              // 2560 16B chunks / 256 threads
        int c = tid + j * NTHREADS;
        if (c < 2048) {                         // A: 256 rows x 8 chunks
            int row = c >> 3, ch = c & 7;
            const unsigned short* g = Xp + (size_t)row * INF + kcol + ch * 8;
            cp_async_16(stage + SMEM_SWIZZLE_128B(row * 128 + ch * 16), g);
        } else {                                // B: 64 rows x 8 chunks
            int cc = c - 2048;
            int row = cc >> 3, ch = cc & 7;
            const unsigned short* g = Wp + (size_t)row * INF + kcol + ch * 8;
            cp_async_16(stage + A_BYTES + SMEM_SWIZZLE_128B(row * 128 + ch * 16), g);
        }
    }
    CP_ASYNC_COMMIT();
}

__global__ void __launch_bounds__(NTHREADS, 2)
gemm_kernel(const float* __restrict__ bias, float* __restrict__ out) {
    extern __shared__ char smem[];
    const uint32_t sbase = smem_to_u32(smem);
    const int tid  = threadIdx.x;
    const int wid  = tid >> 5;
    const int lane = tid & 31;
    const int wm = wid & 3;       // 4 warps along M (64 rows each)
    const int wn = wid >> 2;      // 2 warps along N (32 cols each)

    // L2-friendly raster: GROUP=16 m-tiles per n-sweep
    const int grid_n = OUTF / CTA_N;   // 64
    const int GROUP  = 16;
    const int per    = GROUP * grid_n; // 1024
    const int g      = blockIdx.x / per;
    const int rem    = blockIdx.x % per;
    const int mtile  = g * GROUP + (rem % GROUP);
    const int ntile  = rem / GROUP;
    const int m0 = mtile * CTA_M;
    const int n0 = ntile * CTA_N;

    const unsigned short* Xp = g_Xh + (size_t)m0 * INF;
    const unsigned short* Wp = reinterpret_cast<const unsigned short*>(g_Wh)
                             + (size_t)n0 * INF;

    // per-lane ldmatrix base offsets (pre-swizzle)
    const int a_base = (wm * 64 + (lane & 15)) * 128 + ((lane >> 4) << 4);
    const int b_base = (wn * 32 + ((lane >> 4) << 3) + (lane & 7)) * 128
                     + (((lane >> 3) & 1) << 4);

    float acc[4][4][4];
#pragma unroll
    for (int mt = 0; mt < 4; mt++)
#pragma unroll
        for (int nt = 0; nt < 4; nt++)
#pragma unroll
            for (int k = 0; k < 4; k++) acc[mt][nt][k] = 0.f;

    // prologue: load first K-tile into slot 0
    load_stage(sbase, tid, Xp, Wp, 0, 0);

    uint32_t a[2][4][4], b[2][2][4];

    for (int it = 0; it < KITERS; it++) {
        CP_ASYNC_WAIT(0);            // tile `it` fully resident
        __syncthreads();             // all warps finished reading the other slot

        const uint32_t S   = sbase + (it & 1) * STAGE_BYTES;
        const uint32_t SBB = S + A_BYTES;

        // preload sub-step 0 fragments FIRST (critical path for the MMAs)
#pragma unroll
        for (int mt = 0; mt < 4; mt++)
            ldsm_x4(a[0][mt], S + SMEM_SWIZZLE_128B(a_base + mt * 2048));
#pragma unroll
        for (int bt = 0; bt < 2; bt++)
            ldsm_x4(b[0][bt], SBB + SMEM_SWIZZLE_128B(b_base + bt * 2048));

        // then kick off the next K-tile load into the other slot
        if (it + 1 < KITERS)
            load_stage(sbase, tid, Xp, Wp, (it + 1) & 1, it + 1);
        else
            CP_ASYNC_COMMIT();       // keep group bookkeeping uniform

        // 4 sub-steps of K=16, register double-buffered
#pragma unroll
        for (int ks = 0; ks < 4; ks++) {
            const int cur = ks & 1, nxt = cur ^ 1;
            if (ks < 3) {            // prefetch ks+1 fragments behind the mmas
#pragma unroll
                for (int mt = 0; mt < 4; mt++)
                    ldsm_x4(a[nxt][mt],
                            S + SMEM_SWIZZLE_128B(a_base + mt * 2048 + (ks + 1) * 32));
#pragma unroll
                for (int bt = 0; bt < 2; bt++)
                    ldsm_x4(b[nxt][bt],
                            SBB + SMEM_SWIZZLE_128B(b_base + bt * 2048 + (ks + 1) * 32));
            }
#pragma unroll
            for (int mt = 0; mt < 4; mt++)
#pragma unroll
                for (int nt = 0; nt < 4; nt++) {
                    int bt = nt >> 1, pr = nt & 1;
                    mma16816(acc[mt][nt], a[cur][mt],
                             b[cur][bt][pr * 2], b[cur][bt][pr * 2 + 1]);
                }
        }
    }

    // ---------------- epilogue: add bias, store f32 -------------------------
    {
        float2 bv[4];
#pragma unroll
        for (int nt = 0; nt < 4; nt++) {
            int n = n0 + wn * 32 + nt * 8 + (lane & 3) * 2;
            bv[nt].x = __ldg(bias + n);
            bv[nt].y = __ldg(bias + n + 1);
        }
#pragma unroll
        for (int mt = 0; mt < 4; mt++) {
#pragma unroll
            for (int r = 0; r < 2; r++) {
                int row = m0 + wm * 64 + mt * 16 + (lane >> 2) + r * 8;
                float* orow = out + (size_t)row * OUTF + n0 + wn * 32 + (lane & 3) * 2;
#pragma unroll
                for (int nt = 0; nt < 4; nt++) {
                    float2 v;
                    v.x = acc[mt][nt][r * 2 + 0] + bv[nt].x;
                    v.y = acc[mt][nt][r * 2 + 1] + bv[nt].y;
                    *reinterpret_cast<float2*>(orow + nt * 8) = v;
                }
            }
        }
    }
}

// ---------------- launcher --------------------------------------------------
extern "C" void kernel_launch(void* const* d_in, const int* in_sizes, int n_in,
                              void* d_out, int out_size) {
    const float* x    = (const float*)d_in[0];      // [8192, 4096] f32
    const float* w    = (const float*)d_in[1];      // [NNZ] f32
    const float* bias = (const float*)d_in[2];      // [4096] f32
    const void*  idx  = d_in[3];                    // [2, NNZ] int32 OR int64
    float* out = (float*)d_out;                     // [8192, 4096] f32
    const int nnz = in_sizes[1];

    // 1) reset dtype flag
    flag_reset_kernel<<<1, 32>>>();
    // 2) fused prep: convert x, zero fp16 W, detect int32-vs-int64 indices
    const int ndet = nnz < 65536 ? nnz : 65536;
    fused_prep_kernel<<<CONV_BLOCKS + ZERO_BLOCKS + DET_BLOCKS, 256>>>(
        x, (const long long*)idx, ndet);
    // 3) scatter-add COO straight into fp16 W (duplicates summed, f16 atomics)
    scatter_kernel<<<(nnz + 255) / 256, 256>>>(idx, w, nnz);

    // 4) HMMA GEMM: out = x @ W^T + bias  (2 CTAs per SM)
    cudaFuncSetAttribute(gemm_kernel,
                         cudaFuncAttributeMaxDynamicSharedMemorySize, GEMM_SMEM);
    const int grid = (TOKENS / CTA_M) * (OUTF / CTA_N);  // 32 * 64 = 2048
    gemm_kernel<<<grid, NTHREADS, GEMM_SMEM>>>(bias, out);
}

// round 16
// speedup vs baseline: 1.2468x; 1.2468x over previous
#include <cuda_runtime.h>
#include <cuda_fp16.h>
#include <cstdint>

// Problem constants (fixed shapes per reference)
#define TOKENS 8192
#define INF    4096
#define OUTF   4096

// ---------------- device scratch (static globals; no runtime allocation) ----
__device__ __half         g_Wh[(size_t)OUTF * INF];     // 32 MiB fp16 W (scatter target)
__device__ unsigned short g_Xh[(size_t)TOKENS * INF];   // 64 MiB fp16 x
__device__ int            g_idx32_flag;                 // 1 => indices are int32

// ---------------- helpers ---------------------------------------------------
__device__ __forceinline__ uint32_t smem_to_u32(const void* p) {
    uint32_t a;
    asm("{ .reg .u64 t; cvta.to.shared.u64 t, %1; cvt.u32.u64 %0, t; }"
        : "=r"(a) : "l"(p));
    return a;
}

#define SMEM_SWIZZLE_128B(byte_offset) \
    ((byte_offset) ^ (((byte_offset) >> 3) & 0x70))

__device__ __forceinline__ void cp_async_16(uint32_t saddr, const void* gaddr) {
    asm volatile("cp.async.cg.shared.global [%0], [%1], 16;"
                 :: "r"(saddr), "l"(gaddr) : "memory");
}

// mbarrier primitives (baseline PTX, sm_80/sm_90 features, valid on sm_103)
__device__ __forceinline__ void mbar_init(uint32_t mbar, uint32_t count) {
    asm volatile("mbarrier.init.shared.b64 [%0], %1;"
                 :: "r"(mbar), "r"(count) : "memory");
}
__device__ __forceinline__ void mbar_arrive(uint32_t mbar) {
    asm volatile("mbarrier.arrive.shared.b64 _, [%0];" :: "r"(mbar) : "memory");
}
// Arrive on mbar once all of THIS thread's prior cp.async ops complete.
// .noinc: do NOT bump the pending count -- the expected count set at init
// already accounts for this thread's arrival. (The default incrementing
// variant nets to zero per thread and the barrier never flips: R15 deadlock.)
__device__ __forceinline__ void cp_async_mbar_arrive_noinc(uint32_t mbar) {
    asm volatile("cp.async.mbarrier.arrive.noinc.shared.b64 [%0];"
                 :: "r"(mbar) : "memory");
}
__device__ __forceinline__ void mbar_wait_parity(uint32_t mbar, uint32_t parity) {
    uint32_t done;
    asm volatile(
        "{\n\t.reg .pred p;\n\t"
        "mbarrier.try_wait.parity.shared.b64 p, [%1], %2;\n\t"
        "selp.b32 %0, 1, 0, p;\n\t}"
        : "=r"(done) : "r"(mbar), "r"(parity) : "memory");
    if (!done) {
        asm volatile(
            "{\n\t.reg .pred P1;\n\t"
            "WAIT_LOOP_%=:\n\t"
            "mbarrier.try_wait.parity.shared.b64 P1, [%0], %1, 0x989680;\n\t"
            "@P1 bra.uni WAIT_DONE_%=;\n\t"
            "bra.uni WAIT_LOOP_%=;\n\t"
            "WAIT_DONE_%=:\n\t}"
            :: "r"(mbar), "r"(parity) : "memory");
    }
}

__device__ __forceinline__ void ldsm_x4(uint32_t r[4], uint32_t addr) {
    asm volatile("ldmatrix.sync.aligned.m8n8.x4.shared.b16 {%0,%1,%2,%3}, [%4];"
                 : "=r"(r[0]), "=r"(r[1]), "=r"(r[2]), "=r"(r[3]) : "r"(addr));
}

__device__ __forceinline__ void mma16816(float c[4], const uint32_t a[4],
                                         uint32_t b0, uint32_t b1) {
    asm volatile(
        "mma.sync.aligned.m16n8k16.row.col.f32.f16.f16.f32 "
        "{%0,%1,%2,%3}, {%4,%5,%6,%7}, {%8,%9}, {%0,%1,%2,%3};"
        : "+f"(c[0]), "+f"(c[1]), "+f"(c[2]), "+f"(c[3])
        : "r"(a[0]), "r"(a[1]), "r"(a[2]), "r"(a[3]), "r"(b0), "r"(b1));
}

// ---------------- prep kernels ---------------------------------------------
__global__ void flag_reset_kernel() {
    if (threadIdx.x == 0) g_idx32_flag = 0;
}

__device__ __forceinline__ uint2 f4_to_h4(float4 v) {
    __half2 lo = __floats2half2_rn(v.x, v.y);
    __half2 hi = __floats2half2_rn(v.z, v.w);
    uint2 o;
    o.x = *reinterpret_cast<uint32_t*>(&lo);
    o.y = *reinterpret_cast<uint32_t*>(&hi);
    return o;
}

// One block-partitioned kernel running three independent DRAM-bound jobs
// concurrently: convert x -> fp16, zero fp16 W, detect index dtype on a 64K
// prefix (true-int64 row indices are < OUTF; packed-int32 pairs overflow).
static constexpr int CONV_BLOCKS = 8192;
static constexpr int ZERO_BLOCKS = 1024;
static constexpr int DET_BLOCKS  = 256;

__global__ void fused_prep_kernel(const float* __restrict__ x,
                                  const long long* __restrict__ idx, int ndet) {
    const int b = blockIdx.x;
    if (b < CONV_BLOCKS) {
        size_t i = (size_t)b * 256 + threadIdx.x;
        const size_t stride = (size_t)CONV_BLOCKS * 256;
        float4 v0 = reinterpret_cast<const float4*>(x)[i];
        float4 v1 = reinterpret_cast<const float4*>(x)[i + stride];
        float4 v2 = reinterpret_cast<const float4*>(x)[i + 2 * stride];
        float4 v3 = reinterpret_cast<const float4*>(x)[i + 3 * stride];
        reinterpret_cast<uint2*>(g_Xh)[i]              = f4_to_h4(v0);
        reinterpret_cast<uint2*>(g_Xh)[i + stride]     = f4_to_h4(v1);
        reinterpret_cast<uint2*>(g_Xh)[i + 2 * stride] = f4_to_h4(v2);
        reinterpret_cast<uint2*>(g_Xh)[i + 3 * stride] = f4_to_h4(v3);
    } else if (b < CONV_BLOCKS + ZERO_BLOCKS) {
        size_t i = (size_t)(b - CONV_BLOCKS) * 256 + threadIdx.x;
        const size_t stride = (size_t)ZERO_BLOCKS * 256;
        uint4 z = make_uint4(0u, 0u, 0u, 0u);
#pragma unroll
        for (int j = 0; j < 8; j++)
            reinterpret_cast<uint4*>(g_Wh)[i + j * stride] = z;
    } else {
        int i = (b - CONV_BLOCKS - ZERO_BLOCKS) * 256 + threadIdx.x;
        if (i < ndet) {
            long long v = idx[i];
            if (v < 0 || v >= OUTF) atomicOr(&g_idx32_flag, 1);
        }
    }
}

// Scatter-add COO directly into fp16 W (duplicates summed via f16 atomics).
__global__ void scatter_kernel(const void* __restrict__ idx_raw,
                               const float* __restrict__ w, int nnz) {
    int i = blockIdx.x * blockDim.x + threadIdx.x;
    if (i >= nnz) return;
    long long r, c;
    if (g_idx32_flag) {
        const int* p = (const int*)idx_raw;
        r = p[i];
        c = p[(size_t)nnz + i];
    } else {
        const long long* p = (const long long*)idx_raw;
        r = p[i];
        c = p[(size_t)nnz + i];
    }
    if (r >= 0 && r < OUTF && c >= 0 && c < INF)
        atomicAdd(&g_Wh[(size_t)r * INF + c], __float2half(w[i]));
}

// ---------------- GEMM kernel (mma.sync m16n8k16, mbarrier pipeline) --------
// CTA tile 256(M) x 128(N) x 64(K); 256 threads = 8 warps as 4(M) x 2(N),
// warp tile 64x64 (the proven best compute core). 3-stage cp.async ring with
// per-stage mbarriers instead of __syncthreads: full[s] (count 256, flipped by
// cp.async.mbarrier.arrive.noinc = data readiness + visibility), empty[s]
// (count 8, one arrive per warp after its last fragment use = WAR protection).
// Warps slip up to two iterations relative to each other, covering the
// fragment preload chains and wait latencies that idle the tensor pipe when
// every warp stalls at one __syncthreads.

static constexpr int CTA_M  = 256;
static constexpr int CTA_N  = 128;
static constexpr int CTA_K  = 64;
static constexpr int KITERS = INF / CTA_K;   // 64
static constexpr int NTHREADS = 256;
static constexpr int STAGES = 3;

static constexpr int A_BYTES      = CTA_M * CTA_K * 2;   // 32768
static constexpr int B_BYTES      = CTA_N * CTA_K * 2;   // 16384
static constexpr int STAGE_BYTES  = A_BYTES + B_BYTES;   // 49152
static constexpr int SM_STAGE0    = 1024;                // mbarriers below
static constexpr int GEMM_SMEM    = SM_STAGE0 + STAGES * STAGE_BYTES; // 148480

// mbarrier smem offsets: full[s] at 16*s, empty[s] at 16*s+8
#define FULL_MBAR(sb, s)  ((sb) + 16 * (s))
#define EMPTY_MBAR(sb, s) ((sb) + 16 * (s) + 8)

__device__ __forceinline__ void load_stage(uint32_t sbase, int tid,
                                           const unsigned short* __restrict__ Xp,
                                           const unsigned short* __restrict__ Wp,
                                           int slot, int kb) {
    const uint32_t stage = sbase + SM_STAGE0 + slot * STAGE_BYTES;
    const int kcol = kb * CTA_K;
#pragma unroll
    for (int j = 0; j < 12; j++) {              // 3072 16B chunks / 256 threads
        int c = tid + j * NTHREADS;
        if (c < 2048) {                         // A: 256 rows x 8 chunks
            int row = c >> 3, ch = c & 7;
            const unsigned short* g = Xp + (size_t)row * INF + kcol + ch * 8;
            cp_async_16(stage + SMEM_SWIZZLE_128B(row * 128 + ch * 16), g);
        } else {                                // B: 128 rows x 8 chunks
            int cc = c - 2048;
            int row = cc >> 3, ch = cc & 7;
            const unsigned short* g = Wp + (size_t)row * INF + kcol + ch * 8;
            cp_async_16(stage + A_BYTES + SMEM_SWIZZLE_128B(row * 128 + ch * 16), g);
        }
    }
    // arrive on full[slot] once this thread's copies above have completed
    cp_async_mbar_arrive_noinc(FULL_MBAR(sbase, slot));
}

__global__ void __launch_bounds__(NTHREADS, 1)
gemm_kernel(const float* __restrict__ bias, float* __restrict__ out) {
    extern __shared__ char smem[];
    const uint32_t sbase = smem_to_u32(smem);
    const int tid  = threadIdx.x;
    const int wid  = tid >> 5;
    const int lane = tid & 31;
    const int wm = wid & 3;       // 4 warps along M (64 rows each)
    const int wn = wid >> 2;      // 2 warps along N (64 cols each)

    // L2-friendly raster: GROUP=16 m-tiles per n-sweep
    const int grid_n = OUTF / CTA_N;   // 32
    const int GROUP  = 16;
    const int per    = GROUP * grid_n; // 512
    const int g      = blockIdx.x / per;
    const int rem    = blockIdx.x % per;
    const int mtile  = g * GROUP + (rem % GROUP);
    const int ntile  = rem / GROUP;
    const int m0 = mtile * CTA_M;
    const int n0 = ntile * CTA_N;

    const unsigned short* Xp = g_Xh + (size_t)m0 * INF;
    const unsigned short* Wp = reinterpret_cast<const unsigned short*>(g_Wh)
                             + (size_t)n0 * INF;

    // init mbarriers, then one (and only) CTA-wide sync
    if (tid == 0) {
#pragma unroll
        for (int s = 0; s < STAGES; s++) {
            mbar_init(FULL_MBAR(sbase, s), NTHREADS);
            mbar_init(EMPTY_MBAR(sbase, s), 8);
        }
    }
    __syncthreads();

    // per-lane ldmatrix base offsets (pre-swizzle, within A / B regions)
    const int a_base = (wm * 64 + (lane & 15)) * 128 + ((lane >> 4) << 4);
    const int b_base = (wn * 64 + ((lane >> 4) << 3) + (lane & 7)) * 128
                     + (((lane >> 3) & 1) << 4);

    float acc[4][8][4];
#pragma unroll
    for (int mt = 0; mt < 4; mt++)
#pragma unroll
        for (int nt = 0; nt < 8; nt++)
#pragma unroll
            for (int k = 0; k < 4; k++) acc[mt][nt][k] = 0.f;

    // prologue: fill stages 0 and 1 (tiles 0 and 1)
    load_stage(sbase, tid, Xp, Wp, 0, 0);
    load_stage(sbase, tid, Xp, Wp, 1, 1);

    uint32_t a[2][4][4], b[2][4][4];
    int cons_s = 0, cons_p = 0;   // consumer cursor (stage, phase parity)

    for (int it = 0; it < KITERS; it++) {
        const uint32_t S   = sbase + SM_STAGE0 + cons_s * STAGE_BYTES;
        const uint32_t SBB = S + A_BYTES;

        // wait for tile `it` data (cp.async completion + visibility)
        mbar_wait_parity(FULL_MBAR(sbase, cons_s), cons_p);

        // preload sub-step 0 fragments FIRST (critical path for the MMAs)
#pragma unroll
        for (int mt = 0; mt < 4; mt++)
            ldsm_x4(a[0][mt], S + SMEM_SWIZZLE_128B(a_base + mt * 2048));
#pragma unroll
        for (int bt = 0; bt < 4; bt++)
            ldsm_x4(b[0][bt], SBB + SMEM_SWIZZLE_128B(b_base + bt * 2048));

        // produce tile it+2 into its ring slot
        const int t = it + 2;
        if (t < KITERS) {
            const int s2 = t % 3;
            const int r  = t / 3;           // reuse index of that slot
            if (t >= STAGES)                // wait for r-th consumption done
                mbar_wait_parity(EMPTY_MBAR(sbase, s2), (r - 1) & 1);
            load_stage(sbase, tid, Xp, Wp, s2, t);
        }

        // 4 sub-steps of K=16, register double-buffered
#pragma unroll
        for (int ks = 0; ks < 4; ks++) {
            const int cur = ks & 1, nxt = cur ^ 1;
            if (ks < 3) {            // prefetch ks+1 fragments behind the mmas
#pragma unroll
                for (int mt = 0; mt < 4; mt++)
                    ldsm_x4(a[nxt][mt],
                            S + SMEM_SWIZZLE_128B(a_base + mt * 2048 + (ks + 1) * 32));
#pragma unroll
                for (int bt = 0; bt < 4; bt++)
                    ldsm_x4(b[nxt][bt],
                            SBB + SMEM_SWIZZLE_128B(b_base + bt * 2048 + (ks + 1) * 32));
            }
#pragma unroll
            for (int mt = 0; mt < 4; mt++)
#pragma unroll
                for (int nt = 0; nt < 8; nt++) {
                    int bt = nt >> 1, pr = nt & 1;
                    mma16816(acc[mt][nt], a[cur][mt],
                             b[cur][bt][pr * 2], b[cur][bt][pr * 2 + 1]);
                }
        }

        // this warp is done reading stage cons_s
        if (lane == 0) mbar_arrive(EMPTY_MBAR(sbase, cons_s));
        if (++cons_s == STAGES) { cons_s = 0; cons_p ^= 1; }
    }

    // ---------------- epilogue: add bias, store f32 -------------------------
    {
        float2 bv[8];
#pragma unroll
        for (int nt = 0; nt < 8; nt++) {
            int n = n0 + wn * 64 + nt * 8 + (lane & 3) * 2;
            bv[nt].x = __ldg(bias + n);
            bv[nt].y = __ldg(bias + n + 1);
        }
#pragma unroll
        for (int mt = 0; mt < 4; mt++) {
#pragma unroll
            for (int r = 0; r < 2; r++) {
                int row = m0 + wm * 64 + mt * 16 + (lane >> 2) + r * 8;
                float* orow = out + (size_t)row * OUTF + n0 + wn * 64 + (lane & 3) * 2;
#pragma unroll
                for (int nt = 0; nt < 8; nt++) {
                    float2 v;
                    v.x = acc[mt][nt][r * 2 + 0] + bv[nt].x;
                    v.y = acc[mt][nt][r * 2 + 1] + bv[nt].y;
                    *reinterpret_cast<float2*>(orow + nt * 8) = v;
                }
            }
        }
    }
}

// ---------------- launcher --------------------------------------------------
extern "C" void kernel_launch(void* const* d_in, const int* in_sizes, int n_in,
                              void* d_out, int out_size) {
    const float* x    = (const float*)d_in[0];      // [8192, 4096] f32
    const float* w    = (const float*)d_in[1];      // [NNZ] f32
    const float* bias = (const float*)d_in[2];      // [4096] f32
    const void*  idx  = d_in[3];                    // [2, NNZ] int32 OR int64
    float* out = (float*)d_out;                     // [8192, 4096] f32
    const int nnz = in_sizes[1];

    // 1) reset dtype flag
    flag_reset_kernel<<<1, 32>>>();
    // 2) fused prep: convert x, zero fp16 W, detect int32-vs-int64 indices
    const int ndet = nnz < 65536 ? nnz : 65536;
    fused_prep_kernel<<<CONV_BLOCKS + ZERO_BLOCKS + DET_BLOCKS, 256>>>(
        x, (const long long*)idx, ndet);
    // 3) scatter-add COO straight into fp16 W (duplicates summed, f16 atomics)
    scatter_kernel<<<(nnz + 255) / 256, 256>>>(idx, w, nnz);

    // 4) HMMA GEMM with mbarrier pipeline: out = x @ W^T + bias
    cudaFuncSetAttribute(gemm_kernel,
                         cudaFuncAttributeMaxDynamicSharedMemorySize, GEMM_SMEM);
    const int grid = (TOKENS / CTA_M) * (OUTF / CTA_N);  // 32 * 32 = 1024
    gemm_kernel<<<grid, NTHREADS, GEMM_SMEM>>>(bias, out);
}